// round 1
// baseline (speedup 1.0000x reference)
#include <cuda_runtime.h>
#include <math.h>

// Constants
#define G_LEAK   0.1f
#define GBAR_NA  4.0f
#define GBAR_K   1.5f
#define GBAR_M   0.07f
#define E_NA     53.0f
#define E_K      (-107.0f)
#define E_LEAK   (-70.0f)
#define TAU_MAX  600.0f
// CURR_LEVEL / A_SOMA = 0.0005 / (pi * (70e-4)^2)
#define I_IN_ON  3.2481060598838624f

__device__ __forceinline__ float efun(float z) {
    // z/(exp(z)-1), Taylor 1 - z/2 near 0
    if (fabsf(z) < 1e-4f) return 1.0f - 0.5f * z;
    return __fdividef(z, __expf(z) - 1.0f);
}

__device__ __forceinline__ void hh_rhs(float V, float n, float m, float h, float p,
                                       float I_in,
                                       float& dV, float& dn, float& dm, float& dh, float& dp) {
    // rate functions (VT = -60 folded in)
    float a_m = 1.28f * efun(-0.25f * (V + 47.0f));
    float b_m = 1.40f * efun( 0.20f * (V + 20.0f));
    float a_h = 0.128f * __expf(-(V + 43.0f) * (1.0f / 18.0f));
    float b_h = __fdividef(4.0f, 1.0f + __expf(-0.2f * (V + 20.0f)));
    float a_n = 0.16f * efun(-0.20f * (V + 45.0f));
    float b_n = 0.5f * __expf(-(V + 50.0f) * 0.025f);

    float m3 = m * m * m;
    float n2 = n * n;
    float n4 = n2 * n2;

    float ek_v = E_K - V;
    dV = m3 * GBAR_NA * h * (E_NA - V)
       + n4 * GBAR_K * ek_v
       + GBAR_M * p * ek_v
       + G_LEAK * (E_LEAK - V)
       + I_in;

    // dx = a - (a+b)*x
    dn = fmaf(-(a_n + b_n), n, a_n);
    dm = fmaf(-(a_m + b_m), m, a_m);
    dh = fmaf(-(a_h + b_h), h, a_h);

    float v1 = V + 35.0f;
    float p_inf = __fdividef(1.0f, 1.0f + __expf(-0.1f * v1));
    float e = __expf(0.05f * v1);
    // tau_p = 600 / (3.3*e + 1/e);  dp = (p_inf - p) / tau_p
    float denom = fmaf(3.3f, e, __fdividef(1.0f, e));
    dp = (p_inf - p) * denom * (1.0f / TAU_MAX);
}

__global__ void __launch_bounds__(256)
hh_kernel(const int* __restrict__ t,
          const float4* __restrict__ V4,
          const float4* __restrict__ n4_,
          const float4* __restrict__ m4,
          const float4* __restrict__ h4,
          const float4* __restrict__ p4,
          float4* __restrict__ out,   // 5 contiguous segments of B/4 float4 each
          int nvec)                   // = B/4
{
    int i = blockIdx.x * blockDim.x + threadIdx.x;
    if (i >= nvec) return;

    // Front-batch all 5 loads (MLP=5 float4 loads in flight)
    float4 V = V4[i];
    float4 n = n4_[i];
    float4 m = m4[i];
    float4 h = h4[i];
    float4 p = p4[i];

    float I_in = (t[0] > 0) ? I_IN_ON : 0.0f;

    float4 dV, dn, dm, dh, dp;
    hh_rhs(V.x, n.x, m.x, h.x, p.x, I_in, dV.x, dn.x, dm.x, dh.x, dp.x);
    hh_rhs(V.y, n.y, m.y, h.y, p.y, I_in, dV.y, dn.y, dm.y, dh.y, dp.y);
    hh_rhs(V.z, n.z, m.z, h.z, p.z, I_in, dV.z, dn.z, dm.z, dh.z, dp.z);
    hh_rhs(V.w, n.w, m.w, h.w, p.w, I_in, dV.w, dn.w, dm.w, dh.w, dp.w);

    out[i]            = dV;
    out[nvec + i]     = dn;
    out[2 * nvec + i] = dm;
    out[3 * nvec + i] = dh;
    out[4 * nvec + i] = dp;
}

extern "C" void kernel_launch(void* const* d_in, const int* in_sizes, int n_in,
                              void* d_out, int out_size) {
    const int*   t = (const int*)  d_in[0];
    const float* V = (const float*)d_in[1];
    const float* n = (const float*)d_in[2];
    const float* m = (const float*)d_in[3];
    const float* h = (const float*)d_in[4];
    const float* p = (const float*)d_in[5];

    int B = in_sizes[1];          // 8388608
    int nvec = B / 4;             // 2097152

    dim3 block(256);
    dim3 grid((nvec + block.x - 1) / block.x);
    hh_kernel<<<grid, block>>>(t,
                               (const float4*)V, (const float4*)n, (const float4*)m,
                               (const float4*)h, (const float4*)p,
                               (float4*)d_out, nvec);
}

// round 2
// speedup vs baseline: 1.0321x; 1.0321x over previous
#include <cuda_runtime.h>
#include <math.h>

#define LOG2E 1.4426950408889634f
// CURR_LEVEL / A_SOMA = 0.0005 / (pi * (70e-4)^2)
#define I_IN_ON 3.2481060598838624f
#define K_EM5   0.006737946999085467f   // e^{-5}

__device__ __forceinline__ void hh_rhs(float V, float n, float m, float h, float p,
                                       float I_in,
                                       float& dV, float& dn, float& dm, float& dh, float& dp) {
    // ---- shared exponential: g = e^{-0.2(V+20)} ----
    float u20 = V + 20.0f;
    float g   = exp2f(-0.2f * LOG2E * u20);

    // b_m = 1.4 * efun(0.2(V+20));  e^z = 1/g  =>  efun = z*g/(1-g)
    float zbm  = 0.2f * u20;
    float bm_e = __fdividef(zbm * g, 1.0f - g);
    float b_m  = 1.4f * ((fabsf(zbm) < 1e-4f) ? fmaf(-0.5f, zbm, 1.0f) : bm_e);

    // b_h = 4 / (1 + e^{-0.2(V+20)})
    float b_h = __fdividef(4.0f, 1.0f + g);

    // a_n = 0.16 * efun(-0.2(V+45));  e^z = g * e^{-5}
    float zn   = -0.2f * (V + 45.0f);
    float an_e = __fdividef(zn, fmaf(g, K_EM5, -1.0f));
    float a_n  = 0.16f * ((fabsf(zn) < 1e-4f) ? fmaf(-0.5f, zn, 1.0f) : an_e);

    // a_m = 1.28 * efun(-0.25(V+47))
    float zm   = -0.25f * (V + 47.0f);
    float eM   = exp2f(LOG2E * zm);
    float am_e = __fdividef(zm, eM - 1.0f);
    float a_m  = 1.28f * ((fabsf(zm) < 1e-4f) ? fmaf(-0.5f, zm, 1.0f) : am_e);

    // a_h = 0.128 * e^{-(V+43)/18}
    float a_h = 0.128f * exp2f(-(LOG2E / 18.0f) * (V + 43.0f));
    // b_n = 0.5 * e^{-(V+50)/40}
    float b_n = 0.5f * exp2f(-(LOG2E * 0.025f) * (V + 50.0f));

    // ---- dV ----
    float m3 = m * m * m;
    float n2 = n * n;
    float n4 = n2 * n2;
    float ek_v = -107.0f - V;
    dV = m3 * 4.0f * h * (53.0f - V)
       + n4 * 1.5f * ek_v
       + 0.07f * p * ek_v
       + 0.1f * (-70.0f - V)
       + I_in;

    // dx = a - (a+b)*x
    dn = fmaf(-(a_n + b_n), n, a_n);
    dm = fmaf(-(a_m + b_m), m, a_m);
    dh = fmaf(-(a_h + b_h), h, a_h);

    // ---- dp: single divide form ----
    // e = e^{0.05(V+35)}, e2 = e^2
    // dp = (e2 - p(1+e2)) * (3.3 e2 + 1) / (600 * e * (1+e2))
    float v1 = V + 35.0f;
    float e  = exp2f(0.05f * LOG2E * v1);
    float e2 = e * e;
    float one_p_e2 = 1.0f + e2;
    float num = (e2 - p * one_p_e2) * fmaf(3.3f, e2, 1.0f);
    float den = 600.0f * e * one_p_e2;
    dp = __fdividef(num, den);
}

__global__ void __launch_bounds__(256)
hh_kernel(const int* __restrict__ t,
          const float4* __restrict__ V4,
          const float4* __restrict__ n4_,
          const float4* __restrict__ m4,
          const float4* __restrict__ h4,
          const float4* __restrict__ p4,
          float4* __restrict__ out,   // 5 contiguous segments of nvec float4 each
          int nvec)
{
    int i = blockIdx.x * blockDim.x + threadIdx.x;
    if (i >= nvec) return;

    // Front-batch all 5 loads (streaming: read-once data)
    float4 V = __ldcs(V4 + i);
    float4 n = __ldcs(n4_ + i);
    float4 m = __ldcs(m4 + i);
    float4 h = __ldcs(h4 + i);
    float4 p = __ldcs(p4 + i);

    float I_in = (t[0] > 0) ? I_IN_ON : 0.0f;

    float4 dV, dn, dm, dh, dp;
    hh_rhs(V.x, n.x, m.x, h.x, p.x, I_in, dV.x, dn.x, dm.x, dh.x, dp.x);
    hh_rhs(V.y, n.y, m.y, h.y, p.y, I_in, dV.y, dn.y, dm.y, dh.y, dp.y);
    hh_rhs(V.z, n.z, m.z, h.z, p.z, I_in, dV.z, dn.z, dm.z, dh.z, dp.z);
    hh_rhs(V.w, n.w, m.w, h.w, p.w, I_in, dV.w, dn.w, dm.w, dh.w, dp.w);

    __stcs(out + i,            dV);
    __stcs(out + nvec + i,     dn);
    __stcs(out + 2 * nvec + i, dm);
    __stcs(out + 3 * nvec + i, dh);
    __stcs(out + 4 * nvec + i, dp);
}

extern "C" void kernel_launch(void* const* d_in, const int* in_sizes, int n_in,
                              void* d_out, int out_size) {
    const int*   t = (const int*)  d_in[0];
    const float* V = (const float*)d_in[1];
    const float* n = (const float*)d_in[2];
    const float* m = (const float*)d_in[3];
    const float* h = (const float*)d_in[4];
    const float* p = (const float*)d_in[5];

    int B = in_sizes[1];          // 8388608
    int nvec = B / 4;             // 2097152

    dim3 block(256);
    dim3 grid((nvec + block.x - 1) / block.x);
    hh_kernel<<<grid, block>>>(t,
                               (const float4*)V, (const float4*)n, (const float4*)m,
                               (const float4*)h, (const float4*)p,
                               (float4*)d_out, nvec);
}

// round 3
// speedup vs baseline: 1.0352x; 1.0030x over previous
#include <cuda_runtime.h>
#include <math.h>

#define LOG2E 1.4426950408889634f
// CURR_LEVEL / A_SOMA = 0.0005 / (pi * (70e-4)^2)
#define I_IN_ON 3.2481060598838624f
#define K_EM5   0.006737946999085467f   // e^{-5}

__device__ __forceinline__ void hh_rhs(float V, float n, float m, float h, float p,
                                       float I_in,
                                       float& dV, float& dn, float& dm, float& dh, float& dp) {
    // ---- shared exponential: g = e^{-0.2(V+20)} ----
    float u20 = V + 20.0f;
    float g   = exp2f(-0.2f * LOG2E * u20);

    // b_m = 1.4 * efun(0.2(V+20));  e^z = 1/g  =>  efun = z*g/(1-g)
    float zbm  = 0.2f * u20;
    float bm_e = __fdividef(zbm * g, 1.0f - g);
    float b_m  = 1.4f * ((fabsf(zbm) < 1e-4f) ? fmaf(-0.5f, zbm, 1.0f) : bm_e);

    // b_h = 4 / (1 + e^{-0.2(V+20)})
    float b_h = __fdividef(4.0f, 1.0f + g);

    // a_n = 0.16 * efun(-0.2(V+45));  e^z = g * e^{-5}
    float zn   = -0.2f * (V + 45.0f);
    float an_e = __fdividef(zn, fmaf(g, K_EM5, -1.0f));
    float a_n  = 0.16f * ((fabsf(zn) < 1e-4f) ? fmaf(-0.5f, zn, 1.0f) : an_e);

    // a_m = 1.28 * efun(-0.25(V+47))
    float zm   = -0.25f * (V + 47.0f);
    float eM   = exp2f(LOG2E * zm);
    float am_e = __fdividef(zm, eM - 1.0f);
    float a_m  = 1.28f * ((fabsf(zm) < 1e-4f) ? fmaf(-0.5f, zm, 1.0f) : am_e);

    // a_h = 0.128 * e^{-(V+43)/18}
    float a_h = 0.128f * exp2f(-(LOG2E / 18.0f) * (V + 43.0f));
    // b_n = 0.5 * e^{-(V+50)/40}
    float b_n = 0.5f * exp2f(-(LOG2E * 0.025f) * (V + 50.0f));

    // ---- dV ----
    float m3 = m * m * m;
    float n2 = n * n;
    float n4 = n2 * n2;
    float ek_v = -107.0f - V;
    dV = m3 * 4.0f * h * (53.0f - V)
       + n4 * 1.5f * ek_v
       + 0.07f * p * ek_v
       + 0.1f * (-70.0f - V)
       + I_in;

    // dx = a - (a+b)*x
    dn = fmaf(-(a_n + b_n), n, a_n);
    dm = fmaf(-(a_m + b_m), m, a_m);
    dh = fmaf(-(a_h + b_h), h, a_h);

    // ---- dp: single divide form ----
    float v1 = V + 35.0f;
    float e  = exp2f(0.05f * LOG2E * v1);
    float e2 = e * e;
    float one_p_e2 = 1.0f + e2;
    float num = (e2 - p * one_p_e2) * fmaf(3.3f, e2, 1.0f);
    float den = 600.0f * e * one_p_e2;
    dp = __fdividef(num, den);
}

__device__ __forceinline__ void hh_vec4(float4 V, float4 n, float4 m, float4 h, float4 p,
                                        float I_in,
                                        float4& dV, float4& dn, float4& dm, float4& dh, float4& dp) {
    hh_rhs(V.x, n.x, m.x, h.x, p.x, I_in, dV.x, dn.x, dm.x, dh.x, dp.x);
    hh_rhs(V.y, n.y, m.y, h.y, p.y, I_in, dV.y, dn.y, dm.y, dh.y, dp.y);
    hh_rhs(V.z, n.z, m.z, h.z, p.z, I_in, dV.z, dn.z, dm.z, dh.z, dp.z);
    hh_rhs(V.w, n.w, m.w, h.w, p.w, I_in, dV.w, dn.w, dm.w, dh.w, dp.w);
}

__global__ void __launch_bounds__(256)
hh_kernel(const int* __restrict__ t,
          const float4* __restrict__ V4,
          const float4* __restrict__ n4_,
          const float4* __restrict__ m4,
          const float4* __restrict__ h4,
          const float4* __restrict__ p4,
          float4* __restrict__ out,   // 5 contiguous segments of nvec float4 each
          int nvec)                   // total float4 count per array
{
    int nhalf = nvec >> 1;
    int i = blockIdx.x * blockDim.x + threadIdx.x;
    if (i >= nhalf) return;
    int j = i + nhalf;

    // Front-batch all 10 loads (MLP = 10 LDG.128 in flight)
    float4 Va = V4[i];
    float4 na = n4_[i];
    float4 ma = m4[i];
    float4 ha = h4[i];
    float4 pa = p4[i];
    float4 Vb = V4[j];
    float4 nb = n4_[j];
    float4 mb = m4[j];
    float4 hb = h4[j];
    float4 pb = p4[j];

    float I_in = (t[0] > 0) ? I_IN_ON : 0.0f;

    float4 dVa, dna, dma, dha, dpa;
    hh_vec4(Va, na, ma, ha, pa, I_in, dVa, dna, dma, dha, dpa);
    out[i]            = dVa;
    out[nvec + i]     = dna;
    out[2 * nvec + i] = dma;
    out[3 * nvec + i] = dha;
    out[4 * nvec + i] = dpa;

    float4 dVb, dnb, dmb, dhb, dpb;
    hh_vec4(Vb, nb, mb, hb, pb, I_in, dVb, dnb, dmb, dhb, dpb);
    out[j]            = dVb;
    out[nvec + j]     = dnb;
    out[2 * nvec + j] = dmb;
    out[3 * nvec + j] = dhb;
    out[4 * nvec + j] = dpb;
}

extern "C" void kernel_launch(void* const* d_in, const int* in_sizes, int n_in,
                              void* d_out, int out_size) {
    const int*   t = (const int*)  d_in[0];
    const float* V = (const float*)d_in[1];
    const float* n = (const float*)d_in[2];
    const float* m = (const float*)d_in[3];
    const float* h = (const float*)d_in[4];
    const float* p = (const float*)d_in[5];

    int B = in_sizes[1];          // 8388608
    int nvec = B / 4;             // 2097152
    int nthreads = nvec / 2;      // 1048576

    dim3 block(256);
    dim3 grid((nthreads + block.x - 1) / block.x);
    hh_kernel<<<grid, block>>>(t,
                               (const float4*)V, (const float4*)n, (const float4*)m,
                               (const float4*)h, (const float4*)p,
                               (float4*)d_out, nvec);
}